// round 14
// baseline (speedup 1.0000x reference)
#include <cuda_runtime.h>
#include <cuda_bf16.h>
#include <math.h>
#include <stdint.h>

#define BB   8192
#define DD   512
#define HH   8
#define MM   16
#define HDD  64
#define D4X  (4*DD)

// ---------------- scratch (device globals; no allocation allowed) ----------------
__device__ float g_xin [BB*DD];
__device__ float g_y1  [BB*DD];
__device__ float g_q   [BB*DD];
__device__ float g_r   [BB*HH*DD];
__device__ float g_wm  [BB*HH*DD];
__device__ float g_ctx [BB*DD];
__device__ float g_xmid[BB*DD];
__device__ float g_y2  [BB*DD];
__device__ float g_h   [BB*D4X];
__device__ float g_wqT [DD*DD];
__device__ float g_wvT [DD*DD];
__device__ float g_woT [DD*DD];
__device__ float g_w1T [DD*D4X];
__device__ float g_w2T [DD*D4X];

__device__ __forceinline__ float sigmoidf_(float x) { return 1.f / (1.f + expf(-x)); }

// ---------------- warp-MMA helpers (sm_80+ features; valid on base sm_103) ----------------
__device__ __forceinline__ uint32_t smem_u32(const void* p) {
    uint32_t a;
    asm("{ .reg .u64 t; cvta.to.shared.u64 t, %1; cvt.u32.u64 %0, t; }" : "=r"(a) : "l"(p));
    return a;
}
__device__ __forceinline__ void ldm4(uint32_t* r, uint32_t addr) {
    asm volatile("ldmatrix.sync.aligned.m8n8.x4.shared.b16 {%0,%1,%2,%3}, [%4];"
                 : "=r"(r[0]), "=r"(r[1]), "=r"(r[2]), "=r"(r[3]) : "r"(addr));
}
__device__ __forceinline__ void mma16816(float* d, const uint32_t* a, uint32_t b0, uint32_t b1) {
    asm volatile(
        "mma.sync.aligned.m16n8k16.row.col.f32.bf16.bf16.f32 "
        "{%0,%1,%2,%3}, {%4,%5,%6,%7}, {%8,%9}, {%0,%1,%2,%3};"
        : "+f"(d[0]), "+f"(d[1]), "+f"(d[2]), "+f"(d[3])
        : "r"(a[0]), "r"(a[1]), "r"(a[2]), "r"(a[3]), "r"(b0), "r"(b1));
}
__device__ __forceinline__ uint32_t packbf(float a, float b) {
    __nv_bfloat162 t = __floats2bfloat162_rn(a, b);
    return *reinterpret_cast<uint32_t*>(&t);
}
__device__ __forceinline__ float bfhi(float x) { return __bfloat162float(__float2bfloat16(x)); }
__device__ __forceinline__ void sts_v4(uint32_t a, uint32_t x, uint32_t y, uint32_t z, uint32_t w) {
    asm volatile("st.shared.v4.b32 [%0], {%1,%2,%3,%4};" :: "r"(a), "r"(x), "r"(y), "r"(z), "r"(w) : "memory");
}
__device__ __forceinline__ void sts_v2(uint32_t a, uint32_t x, uint32_t y) {
    asm volatile("st.shared.v2.b32 [%0], {%1,%2};" :: "r"(a), "r"(x), "r"(y) : "memory");
}

// store 8 fp32 (two float4) as bf16 hi-plane + lo-plane, 16B each
__device__ __forceinline__ void split8(uint32_t hiA, uint32_t loA, float4 v0, float4 v1) {
    float h0 = bfhi(v0.x), h1 = bfhi(v0.y), h2 = bfhi(v0.z), h3 = bfhi(v0.w);
    float h4 = bfhi(v1.x), h5 = bfhi(v1.y), h6 = bfhi(v1.z), h7 = bfhi(v1.w);
    sts_v4(hiA, packbf(h0,h1), packbf(h2,h3), packbf(h4,h5), packbf(h6,h7));
    sts_v4(loA, packbf(v0.x-h0, v0.y-h1), packbf(v0.z-h2, v0.w-h3),
                packbf(v1.x-h4, v1.y-h5), packbf(v1.z-h6, v1.w-h7));
}
__device__ __forceinline__ void split4(uint32_t hiA, uint32_t loA, float4 v) {
    float h0 = bfhi(v.x), h1 = bfhi(v.y), h2 = bfhi(v.z), h3 = bfhi(v.w);
    sts_v2(hiA, packbf(h0,h1), packbf(h2,h3));
    sts_v2(loA, packbf(v.x-h0, v.y-h1), packbf(v.z-h2, v.w-h3));
}

// ---------------- tensor-core GEMM (HMMA bf16, 3-term split, fp32 acc) ----------------
// C[128*by+m][bx*NT + c_zcol*bz + n] = sum_k A[m][a_zcol*bz+k] * Bt[bx*NT + bt_zrow*bz + n][bt_zcol*bz + k]
// EPI: 0 +bias; 1 +bias+res; 2 +bias,gelu; 3 +bias+res + gated ssum; 4 none
template<int NT, int EPI>
__global__ void __launch_bounds__(256) tgemm(
    const float* __restrict__ A, int lda, int a_zcol,
    const float* __restrict__ Bt, int ldb, int bt_zrow, int bt_zcol,
    const float* __restrict__ bias, const float* __restrict__ res,
    float* __restrict__ C, int ldc, int c_zcol, int K,
    const float* __restrict__ ss_in, const float* __restrict__ lam,
    float* __restrict__ ss_out)
{
    constexpr int WM = (NT == 128) ? 64 : 32;      // warp tile M
    constexpr int MF = WM / 16;                     // m16 fragments per warp
    constexpr int AP = 128 * 48;                    // A plane bytes (rows x 24 bf16)
    constexpr int BP = NT * 48;                     // B plane bytes
    constexpr int STG = 2 * AP + 2 * BP;            // one buffer: aHi,aLo,bHi,bLo

    extern __shared__ char smemraw[];
    const uint32_t smb = smem_u32(smemraw);

    const int tid  = threadIdx.x;
    const int lane = tid & 31;
    const int wid  = tid >> 5;
    const int wm   = (NT == 128) ? (wid & 1) : (wid & 3);
    const int wn   = (NT == 128) ? (wid >> 1) : (wid >> 2);

    const int m0 = blockIdx.y * 128;
    const int bz = blockIdx.z;
    const float* Ab = A  + a_zcol * bz + (size_t)m0 * lda;
    const float* Bb = Bt + (size_t)(blockIdx.x * NT + bt_zrow * bz) * ldb + bt_zcol * bz;

    // per-thread global->smem mapping for one k16 chunk
    const int arow = tid >> 1, akoff = (tid & 1) * 8;
    const float* Apt = Ab + (size_t)arow * lda + akoff;
    const uint32_t aoff = arow * 48 + akoff * 2;
    int brow, bkoff;
    if (NT == 128) { brow = tid >> 1; bkoff = (tid & 1) * 8; }
    else           { brow = tid >> 2; bkoff = (tid & 3) * 4; }
    const float* Bpt = Bb + (size_t)brow * ldb + bkoff;
    const uint32_t boff = brow * 48 + bkoff * 2;

    float acc[MF][4][4];
#pragma unroll
    for (int i = 0; i < MF; i++)
#pragma unroll
        for (int j = 0; j < 4; j++)
#pragma unroll
            for (int e = 0; e < 4; e++) acc[i][j][e] = 0.f;

    const int nc = K >> 4;
    float4 ra0, ra1, rb0, rb1;

    // prologue: chunk 0 -> buf 0
    ra0 = *(const float4*)(Apt);
    ra1 = *(const float4*)(Apt + 4);
    rb0 = *(const float4*)(Bpt);
    if (NT == 128) rb1 = *(const float4*)(Bpt + 4);
    {
        uint32_t b0 = smb;
        split8(b0 + aoff, b0 + AP + aoff, ra0, ra1);
        if (NT == 128) split8(b0 + 2*AP + boff, b0 + 2*AP + BP + boff, rb0, rb1);
        else           split4(b0 + 2*AP + boff, b0 + 2*AP + BP + boff, rb0);
    }
    __syncthreads();

    for (int c = 0; c < nc; c++) {
        if (c + 1 < nc) {
            const int kc = (c + 1) * 16;
            ra0 = *(const float4*)(Apt + kc);
            ra1 = *(const float4*)(Apt + kc + 4);
            rb0 = *(const float4*)(Bpt + kc);
            if (NT == 128) rb1 = *(const float4*)(Bpt + kc + 4);
        }
        // ---- compute on buffer c&1 ----
        const uint32_t bse = smb + (c & 1) * STG;
        uint32_t afh[MF][4], afl[MF][4];
#pragma unroll
        for (int mf = 0; mf < MF; mf++) {
            uint32_t ad = bse + (wm * WM + mf * 16 + (lane & 15)) * 48 + ((lane >> 4) << 4);
            ldm4(afh[mf], ad);
            ldm4(afl[mf], ad + AP);
        }
        uint32_t bfh[2][4], bfl[2][4];
#pragma unroll
        for (int p = 0; p < 2; p++) {
            uint32_t bd = bse + 2*AP
                        + (wn * 32 + p * 16 + (lane & 7) + ((lane & 16) >> 1)) * 48
                        + ((lane & 8) << 1);
            ldm4(bfh[p], bd);
            ldm4(bfl[p], bd + BP);
        }
#pragma unroll
        for (int mf = 0; mf < MF; mf++)
#pragma unroll
            for (int nf = 0; nf < 4; nf++) {
                const int p = nf >> 1, s = (nf & 1) * 2;
                mma16816(acc[mf][nf], afh[mf], bfh[p][s], bfh[p][s+1]);
                mma16816(acc[mf][nf], afh[mf], bfl[p][s], bfl[p][s+1]);
                mma16816(acc[mf][nf], afl[mf], bfh[p][s], bfh[p][s+1]);
            }
        // ---- stage chunk c+1 into other buffer ----
        if (c + 1 < nc) {
            uint32_t bn = smb + ((c + 1) & 1) * STG;
            split8(bn + aoff, bn + AP + aoff, ra0, ra1);
            if (NT == 128) split8(bn + 2*AP + boff, bn + 2*AP + BP + boff, rb0, rb1);
            else           split4(bn + 2*AP + boff, bn + 2*AP + BP + boff, rb0);
            __syncthreads();
        }
    }

    // ---- epilogue ----
    const int ccol0 = blockIdx.x * NT + c_zcol * bz;
#pragma unroll
    for (int mf = 0; mf < MF; mf++) {
#pragma unroll
        for (int nf = 0; nf < 4; nf++) {
            const int col = ccol0 + wn * 32 + nf * 8 + 2 * (lane & 3);
            float bb0 = 0.f, bb1 = 0.f, sg0 = 0.f, sg1 = 0.f;
            if (EPI != 4) { bb0 = bias[col]; bb1 = bias[col + 1]; }
            if (EPI == 3) {
                sg0 = 1.f / (1.f + expf(-lam[col]));
                sg1 = 1.f / (1.f + expf(-lam[col + 1]));
            }
#pragma unroll
            for (int half = 0; half < 2; half++) {
                const int row = m0 + wm * WM + mf * 16 + (lane >> 2) + half * 8;
                const size_t off = (size_t)row * ldc + col;
                float v0 = acc[mf][nf][2*half]     + bb0;
                float v1 = acc[mf][nf][2*half + 1] + bb1;
                if (EPI == 1 || EPI == 3) {
                    float2 rv = *(const float2*)(res + off);
                    v0 += rv.x; v1 += rv.y;
                }
                if (EPI == 2) {
                    float t0 = tanhf(0.7978845608028654f * (v0 + 0.044715f * v0 * v0 * v0));
                    float t1 = tanhf(0.7978845608028654f * (v1 + 0.044715f * v1 * v1 * v1));
                    v0 = 0.5f * v0 * (1.f + t0);
                    v1 = 0.5f * v1 * (1.f + t1);
                }
                float2 o; o.x = v0; o.y = v1;
                *(float2*)(C + off) = o;
                if (EPI == 3) {
                    float2 si = *(const float2*)(ss_in + off);
                    float2 so;
                    so.x = si.x * sg0 + v0 * (1.f - sg0);
                    so.y = si.y * sg1 + v1 * (1.f - sg1);
                    *(float2*)(ss_out + off) = so;
                }
            }
        }
    }
}

// ---------------- fused: gated input + mem slot 15 + LN1 ----------------
__global__ void k_xin_ln(const float* __restrict__ x, const float* __restrict__ ssum,
                         const float* __restrict__ alpha,
                         const float* __restrict__ scale, const float* __restrict__ bias,
                         float* __restrict__ out_mem, float* __restrict__ xin,
                         float* __restrict__ y1)
{
    int gw   = (blockIdx.x * blockDim.x + threadIdx.x) >> 5;
    int lane = threadIdx.x & 31;
    if (gw >= BB) return;
    const float4* xr = (const float4*)(x    + (size_t)gw * DD);
    const float4* sr = (const float4*)(ssum + (size_t)gw * DD);
    const float4* ar = (const float4*)alpha;
    float4 v[4];
    float s = 0.f;
#pragma unroll
    for (int j = 0; j < 4; j++) {
        float4 xv = xr[lane + 32*j], sv = sr[lane + 32*j], av = ar[lane + 32*j];
        v[j].x = xv.x + sv.x * sigmoidf_(av.x);
        v[j].y = xv.y + sv.y * sigmoidf_(av.y);
        v[j].z = xv.z + sv.z * sigmoidf_(av.z);
        v[j].w = xv.w + sv.w * sigmoidf_(av.w);
        s += v[j].x + v[j].y + v[j].z + v[j].w;
    }
    float4* xo = (float4*)(xin + (size_t)gw * DD);
    float4* mo = (float4*)(out_mem + ((size_t)gw * MM + (MM-1)) * DD);
#pragma unroll
    for (int j = 0; j < 4; j++) { xo[lane + 32*j] = v[j]; mo[lane + 32*j] = v[j]; }
#pragma unroll
    for (int o = 16; o; o >>= 1) s += __shfl_xor_sync(0xffffffffu, s, o);
    float mu = s * (1.f / DD), var = 0.f;
#pragma unroll
    for (int j = 0; j < 4; j++) {
        float a = v[j].x - mu, b = v[j].y - mu, c = v[j].z - mu, d = v[j].w - mu;
        var += a*a + b*b + c*c + d*d;
    }
#pragma unroll
    for (int o = 16; o; o >>= 1) var += __shfl_xor_sync(0xffffffffu, var, o);
    float inv = rsqrtf(var * (1.f / DD) + 1e-6f);
    float4* orow = (float4*)(y1 + (size_t)gw * DD);
    const float4* sc = (const float4*)scale;
    const float4* bi = (const float4*)bias;
#pragma unroll
    for (int j = 0; j < 4; j++) {
        float4 sv = sc[lane + 32*j], bv = bi[lane + 32*j], o4;
        o4.x = (v[j].x - mu) * inv * sv.x + bv.x;
        o4.y = (v[j].y - mu) * inv * sv.y + bv.y;
        o4.z = (v[j].z - mu) * inv * sv.z + bv.z;
        o4.w = (v[j].w - mu) * inv * sv.w + bv.w;
        orow[lane + 32*j] = o4;
    }
}

// ---------------- sliding-window copy ----------------
__global__ void k_copy(const float* __restrict__ mem, float* __restrict__ out_mem)
{
    int i = blockIdx.x * blockDim.x + threadIdx.x;
    const int n = BB * (MM-1) * DD / 4;
    if (i >= n) return;
    const int per_b = (MM-1) * (DD/4);
    int b = i / per_b, r = i - b * per_b;
    int t = r >> 7, d4 = r & (DD/4 - 1);
    ((float4*)out_mem)[(size_t)(b*MM + t) * (DD/4) + d4] =
        ((const float4*)mem)[(size_t)(b*MM + t + 1) * (DD/4) + d4];
}

// ---------------- generic transpose: in[R,C] -> out[C,R] ----------------
__global__ void k_trg(const float* __restrict__ in, float* __restrict__ out, int R, int C)
{
    __shared__ float t[32][33];
    int bx = blockIdx.x * 32, by = blockIdx.y * 32;
#pragma unroll
    for (int i = 0; i < 32; i += 8)
        t[threadIdx.y + i][threadIdx.x] = in[(size_t)(by + threadIdx.y + i) * C + bx + threadIdx.x];
    __syncthreads();
#pragma unroll
    for (int i = 0; i < 32; i += 8)
        out[(size_t)(bx + threadIdx.y + i) * R + by + threadIdx.x] = t[threadIdx.x][threadIdx.y + i];
}

// ---------------- LayerNorm (LN2) ----------------
__global__ void k_ln(const float* __restrict__ in, const float* __restrict__ scale,
                     const float* __restrict__ bias, float* __restrict__ out)
{
    int gw   = (blockIdx.x * blockDim.x + threadIdx.x) >> 5;
    int lane = threadIdx.x & 31;
    if (gw >= BB) return;
    const float4* row = (const float4*)(in + (size_t)gw * DD);
    float4 v[4];
    float s = 0.f;
#pragma unroll
    for (int j = 0; j < 4; j++) {
        v[j] = row[lane + 32*j];
        s += v[j].x + v[j].y + v[j].z + v[j].w;
    }
#pragma unroll
    for (int o = 16; o; o >>= 1) s += __shfl_xor_sync(0xffffffffu, s, o);
    float mu = s * (1.f / DD), var = 0.f;
#pragma unroll
    for (int j = 0; j < 4; j++) {
        float a = v[j].x - mu, b = v[j].y - mu, c = v[j].z - mu, d = v[j].w - mu;
        var += a*a + b*b + c*c + d*d;
    }
#pragma unroll
    for (int o = 16; o; o >>= 1) var += __shfl_xor_sync(0xffffffffu, var, o);
    float inv = rsqrtf(var * (1.f / DD) + 1e-6f);
    float4* orow = (float4*)(out + (size_t)gw * DD);
    const float4* sc = (const float4*)scale;
    const float4* bi = (const float4*)bias;
#pragma unroll
    for (int j = 0; j < 4; j++) {
        float4 sv = sc[lane + 32*j], bv = bi[lane + 32*j], o4;
        o4.x = (v[j].x - mu) * inv * sv.x + bv.x;
        o4.y = (v[j].y - mu) * inv * sv.y + bv.y;
        o4.z = (v[j].z - mu) * inv * sv.z + bv.z;
        o4.w = (v[j].w - mu) * inv * sv.w + bv.w;
        orow[lane + 32*j] = o4;
    }
}

// ---------------- fused attention: block per b, warp per head ----------------
__global__ void __launch_bounds__(256) k_attn2(
    const float* __restrict__ mem2, const float* __restrict__ r,
    const float* __restrict__ q, const float* __restrict__ bk,
    float* __restrict__ wm)
{
    __shared__ float ms[MM][DD];
    const int b = blockIdx.x, tid = threadIdx.x;
    const float4* src = (const float4*)(mem2 + (size_t)b * MM * DD);
    float4* dst = (float4*)ms;
#pragma unroll
    for (int i = 0; i < 8; i++) dst[tid + 256*i] = src[tid + 256*i];
    __syncthreads();
    const int h = tid >> 5, lane = tid & 31;
    float rv[16];
    const float* rp = r + (size_t)b * (HH*DD) + h * DD;
#pragma unroll
    for (int i = 0; i < 16; i++) rv[i] = rp[i*32 + lane];
    const float* qp  = q  + (size_t)b * DD + h * HDD;
    const float* bkp = bk + h * HDD;
    float s0 = qp[lane] * bkp[lane] + qp[lane+32] * bkp[lane+32];
#pragma unroll
    for (int o = 16; o; o >>= 1) s0 += __shfl_xor_sync(0xffffffffu, s0, o);
    float sc[MM];
#pragma unroll
    for (int t = 0; t < MM; t++) {
        float p = 0.f;
#pragma unroll
        for (int i = 0; i < 16; i++) p = fmaf(rv[i], ms[t][i*32 + lane], p);
#pragma unroll
        for (int o = 16; o; o >>= 1) p += __shfl_xor_sync(0xffffffffu, p, o);
        sc[t] = (p + s0) * 0.125f;
    }
    float mx = sc[0];
#pragma unroll
    for (int t = 1; t < MM; t++) mx = fmaxf(mx, sc[t]);
    float sum = 0.f;
#pragma unroll
    for (int t = 0; t < MM; t++) { sc[t] = expf(sc[t] - mx); sum += sc[t]; }
    float inv = 1.f / sum;
    float wv[16];
#pragma unroll
    for (int i = 0; i < 16; i++) wv[i] = 0.f;
#pragma unroll
    for (int t = 0; t < MM; t++) {
        float w = sc[t] * inv;
#pragma unroll
        for (int i = 0; i < 16; i++) wv[i] = fmaf(w, ms[t][i*32 + lane], wv[i]);
    }
    float* wp = wm + (size_t)b * (HH*DD) + h * DD;
#pragma unroll
    for (int i = 0; i < 16; i++) wp[i*32 + lane] = wv[i];
}

// ---------------- launch ----------------
static const int SMEM128 = 2 * (2*128*48 + 2*128*48);   // 49152 B
static const int SMEM64  = 2 * (2*128*48 + 2*64*48);    // 36864 B

extern "C" void kernel_launch(void* const* d_in, const int* in_sizes, int n_in,
                              void* d_out, int out_size)
{
    const float* mem   = (const float*)d_in[0];
    const float* ssum  = (const float*)d_in[1];
    const float* x     = (const float*)d_in[2];
    const float* alpha = (const float*)d_in[3];
    const float* lam   = (const float*)d_in[4];
    const float* ln1s  = (const float*)d_in[5];
    const float* ln1b  = (const float*)d_in[6];
    const float* ln2s  = (const float*)d_in[7];
    const float* ln2b  = (const float*)d_in[8];
    const float* wq    = (const float*)d_in[9];
    const float* bq    = (const float*)d_in[10];
    const float* wk    = (const float*)d_in[11];
    const float* bk    = (const float*)d_in[12];
    const float* wv    = (const float*)d_in[13];
    const float* bv    = (const float*)d_in[14];
    const float* wo    = (const float*)d_in[15];
    const float* bo    = (const float*)d_in[16];
    const float* w1    = (const float*)d_in[17];
    const float* b1    = (const float*)d_in[18];
    const float* w2    = (const float*)d_in[19];
    const float* b2    = (const float*)d_in[20];

    float* out_mem  = (float*)d_out;
    float* out_ssum = out_mem + (size_t)BB * MM * DD;
    float* out_x    = out_ssum + (size_t)BB * DD;

    float *p_xin, *p_y1, *p_q, *p_r, *p_wm, *p_ctx, *p_xmid, *p_y2, *p_h;
    float *p_wqT, *p_wvT, *p_woT, *p_w1T, *p_w2T;
    cudaGetSymbolAddress((void**)&p_xin,  g_xin);
    cudaGetSymbolAddress((void**)&p_y1,   g_y1);
    cudaGetSymbolAddress((void**)&p_q,    g_q);
    cudaGetSymbolAddress((void**)&p_r,    g_r);
    cudaGetSymbolAddress((void**)&p_wm,   g_wm);
    cudaGetSymbolAddress((void**)&p_ctx,  g_ctx);
    cudaGetSymbolAddress((void**)&p_xmid, g_xmid);
    cudaGetSymbolAddress((void**)&p_y2,   g_y2);
    cudaGetSymbolAddress((void**)&p_h,    g_h);
    cudaGetSymbolAddress((void**)&p_wqT,  g_wqT);
    cudaGetSymbolAddress((void**)&p_wvT,  g_wvT);
    cudaGetSymbolAddress((void**)&p_woT,  g_woT);
    cudaGetSymbolAddress((void**)&p_w1T,  g_w1T);
    cudaGetSymbolAddress((void**)&p_w2T,  g_w2T);

    // 1) gated input + mem slot 15 + LN1
    k_xin_ln<<<BB/8, 256>>>(x, ssum, alpha, ln1s, ln1b, out_mem, p_xin, p_y1);
    // 2) shift old memory
    k_copy<<<(BB*(MM-1)*DD/4 + 255) / 256, 256>>>(mem, out_mem);
    // 3) weight transposes (B operands must be [N][K])
    k_trg<<<dim3(16, 16), dim3(32, 8)>>>(wq, p_wqT, DD, DD);
    k_trg<<<dim3(16, 16), dim3(32, 8)>>>(wv, p_wvT, DD, DD);
    k_trg<<<dim3(16, 16), dim3(32, 8)>>>(wo, p_woT, DD, DD);
    k_trg<<<dim3(64, 16), dim3(32, 8)>>>(w1, p_w1T, DD, D4X);
    k_trg<<<dim3(16, 64), dim3(32, 8)>>>(w2, p_w2T, D4X, DD);
    // 4) q = y1 @ wq + bq
    tgemm<128,0><<<dim3(4, 64, 1), 256, SMEM128>>>(p_y1, DD, 0, p_wqT, DD, 0, 0,
        bq, nullptr, p_q, DD, 0, DD, nullptr, nullptr, nullptr);
    // 5) r[b,h,j] = sum_d q[b,h*64+d] * wk[j][h*64+d]
    tgemm<128,4><<<dim3(4, 64, HH), 256, SMEM128>>>(p_q, DD, HDD, wk, DD, 0, HDD,
        nullptr, nullptr, p_r, HH*DD, DD, HDD, nullptr, nullptr, nullptr);
    // 6) attention: softmax over r·mem', weighted memory wm
    k_attn2<<<BB, 256>>>(out_mem, p_r, p_q, bk, p_wm);
    // 7) ctx[b, h*64+n] = wm[b,h,:] @ wvT[h*64+n,:] + bv
    tgemm<64,0><<<dim3(1, 64, HH), 256, SMEM64>>>(p_wm, HH*DD, DD, p_wvT, DD, HDD, 0,
        bv, nullptr, p_ctx, DD, HDD, DD, nullptr, nullptr, nullptr);
    // 8) x_mid = x_in + ctx @ wo + bo
    tgemm<128,1><<<dim3(4, 64, 1), 256, SMEM128>>>(p_ctx, DD, 0, p_woT, DD, 0, 0,
        bo, p_xin, p_xmid, DD, 0, DD, nullptr, nullptr, nullptr);
    // 9) LN2
    k_ln<<<BB/8, 256>>>(p_xmid, ln2s, ln2b, p_y2);
    // 10) h = gelu(y2 @ w1 + b1)
    tgemm<128,2><<<dim3(16, 64, 1), 256, SMEM128>>>(p_y2, DD, 0, p_w1T, DD, 0, 0,
        b1, nullptr, p_h, D4X, 0, DD, nullptr, nullptr, nullptr);
    // 11) x_out = x_mid + h @ w2 + b2 ; new_ssum = ssum*sig(lam) + x_out*(1-sig(lam))
    tgemm<128,3><<<dim3(4, 64, 1), 256, SMEM128>>>(p_h, D4X, 0, p_w2T, D4X, 0, 0,
        b2, p_xmid, out_x, DD, 0, D4X, ssum, lam, out_ssum);
}

// round 15
// speedup vs baseline: 1.0009x; 1.0009x over previous
#include <cuda_runtime.h>
#include <cuda_bf16.h>
#include <math.h>
#include <stdint.h>

#define BB   8192
#define DD   512
#define HH   8
#define MM   16
#define HDD  64
#define D4X  (4*DD)

// ---------------- scratch (device globals; no allocation allowed) ----------------
__device__ float g_xin [BB*DD];
__device__ float g_y1  [BB*DD];
__device__ float g_q   [BB*DD];
__device__ float g_r   [BB*HH*DD];
__device__ float g_wm  [BB*HH*DD];
__device__ float g_ctx [BB*DD];
__device__ float g_xmid[BB*DD];
__device__ float g_y2  [BB*DD];
__device__ float g_h   [BB*D4X];
__device__ float g_wqT [DD*DD];
__device__ float g_wvT [DD*DD];
__device__ float g_woT [DD*DD];
__device__ float g_w1T [DD*D4X];
__device__ float g_w2T [DD*D4X];

__device__ __forceinline__ float sigmoidf_(float x) { return 1.f / (1.f + expf(-x)); }

// ---------------- warp-MMA helpers (sm_80+ features; valid on base sm_103) ----------------
__device__ __forceinline__ uint32_t smem_u32(const void* p) {
    uint32_t a;
    asm("{ .reg .u64 t; cvta.to.shared.u64 t, %1; cvt.u32.u64 %0, t; }" : "=r"(a) : "l"(p));
    return a;
}
__device__ __forceinline__ void ldm4(uint32_t* r, uint32_t addr) {
    asm volatile("ldmatrix.sync.aligned.m8n8.x4.shared.b16 {%0,%1,%2,%3}, [%4];"
                 : "=r"(r[0]), "=r"(r[1]), "=r"(r[2]), "=r"(r[3]) : "r"(addr));
}
__device__ __forceinline__ void mma16816(float* d, const uint32_t* a, uint32_t b0, uint32_t b1) {
    asm volatile(
        "mma.sync.aligned.m16n8k16.row.col.f32.bf16.bf16.f32 "
        "{%0,%1,%2,%3}, {%4,%5,%6,%7}, {%8,%9}, {%0,%1,%2,%3};"
        : "+f"(d[0]), "+f"(d[1]), "+f"(d[2]), "+f"(d[3])
        : "r"(a[0]), "r"(a[1]), "r"(a[2]), "r"(a[3]), "r"(b0), "r"(b1));
}
__device__ __forceinline__ uint32_t packbf(float a, float b) {
    __nv_bfloat162 t = __floats2bfloat162_rn(a, b);
    return *reinterpret_cast<uint32_t*>(&t);
}
__device__ __forceinline__ float bfhi(float x) { return __bfloat162float(__float2bfloat16(x)); }
__device__ __forceinline__ void sts_v4(uint32_t a, uint32_t x, uint32_t y, uint32_t z, uint32_t w) {
    asm volatile("st.shared.v4.b32 [%0], {%1,%2,%3,%4};" :: "r"(a), "r"(x), "r"(y), "r"(z), "r"(w) : "memory");
}
__device__ __forceinline__ void sts_v2(uint32_t a, uint32_t x, uint32_t y) {
    asm volatile("st.shared.v2.b32 [%0], {%1,%2};" :: "r"(a), "r"(x), "r"(y) : "memory");
}

// store 8 fp32 (two float4) as bf16 hi-plane + lo-plane, 16B each
__device__ __forceinline__ void split8(uint32_t hiA, uint32_t loA, float4 v0, float4 v1) {
    float h0 = bfhi(v0.x), h1 = bfhi(v0.y), h2 = bfhi(v0.z), h3 = bfhi(v0.w);
    float h4 = bfhi(v1.x), h5 = bfhi(v1.y), h6 = bfhi(v1.z), h7 = bfhi(v1.w);
    sts_v4(hiA, packbf(h0,h1), packbf(h2,h3), packbf(h4,h5), packbf(h6,h7));
    sts_v4(loA, packbf(v0.x-h0, v0.y-h1), packbf(v0.z-h2, v0.w-h3),
                packbf(v1.x-h4, v1.y-h5), packbf(v1.z-h6, v1.w-h7));
}
__device__ __forceinline__ void split4(uint32_t hiA, uint32_t loA, float4 v) {
    float h0 = bfhi(v.x), h1 = bfhi(v.y), h2 = bfhi(v.z), h3 = bfhi(v.w);
    sts_v2(hiA, packbf(h0,h1), packbf(h2,h3));
    sts_v2(loA, packbf(v.x-h0, v.y-h1), packbf(v.z-h2, v.w-h3));
}

// ---------------- tensor-core GEMM (HMMA bf16, 3-term split, fp32 acc) ----------------
// C[128*by+m][bx*NT + c_zcol*bz + n] = sum_k A[m][a_zcol*bz+k] * Bt[bx*NT + bt_zrow*bz + n][bt_zcol*bz + k]
// EPI: 0 +bias; 1 +bias+res; 2 +bias,gelu; 3 +bias+res + gated ssum; 4 none
template<int NT, int EPI>
__global__ void __launch_bounds__(256) tgemm(
    const float* __restrict__ A, int lda, int a_zcol,
    const float* __restrict__ Bt, int ldb, int bt_zrow, int bt_zcol,
    const float* __restrict__ bias, const float* __restrict__ res,
    float* __restrict__ C, int ldc, int c_zcol, int K,
    const float* __restrict__ ss_in, const float* __restrict__ lam,
    float* __restrict__ ss_out)
{
    constexpr int WM = (NT == 128) ? 64 : 32;      // warp tile M
    constexpr int MF = WM / 16;                     // m16 fragments per warp
    constexpr int AP = 128 * 48;                    // A plane bytes (rows x 24 bf16)
    constexpr int BP = NT * 48;                     // B plane bytes
    constexpr int STG = 2 * AP + 2 * BP;            // one buffer: aHi,aLo,bHi,bLo

    extern __shared__ char smemraw[];
    const uint32_t smb = smem_u32(smemraw);

    const int tid  = threadIdx.x;
    const int lane = tid & 31;
    const int wid  = tid >> 5;
    const int wm   = (NT == 128) ? (wid & 1) : (wid & 3);
    const int wn   = (NT == 128) ? (wid >> 1) : (wid >> 2);

    const int m0 = blockIdx.y * 128;
    const int bz = blockIdx.z;
    const float* Ab = A  + a_zcol * bz + (size_t)m0 * lda;
    const float* Bb = Bt + (size_t)(blockIdx.x * NT + bt_zrow * bz) * ldb + bt_zcol * bz;

    // per-thread global->smem mapping for one k16 chunk
    const int arow = tid >> 1, akoff = (tid & 1) * 8;
    const float* Apt = Ab + (size_t)arow * lda + akoff;
    const uint32_t aoff = arow * 48 + akoff * 2;
    int brow, bkoff;
    if (NT == 128) { brow = tid >> 1; bkoff = (tid & 1) * 8; }
    else           { brow = tid >> 2; bkoff = (tid & 3) * 4; }
    const float* Bpt = Bb + (size_t)brow * ldb + bkoff;
    const uint32_t boff = brow * 48 + bkoff * 2;

    float acc[MF][4][4];
#pragma unroll
    for (int i = 0; i < MF; i++)
#pragma unroll
        for (int j = 0; j < 4; j++)
#pragma unroll
            for (int e = 0; e < 4; e++) acc[i][j][e] = 0.f;

    const int nc = K >> 4;
    float4 ra0, ra1, rb0, rb1;

    // prologue: chunk 0 -> buf 0
    ra0 = *(const float4*)(Apt);
    ra1 = *(const float4*)(Apt + 4);
    rb0 = *(const float4*)(Bpt);
    if (NT == 128) rb1 = *(const float4*)(Bpt + 4);
    {
        uint32_t b0 = smb;
        split8(b0 + aoff, b0 + AP + aoff, ra0, ra1);
        if (NT == 128) split8(b0 + 2*AP + boff, b0 + 2*AP + BP + boff, rb0, rb1);
        else           split4(b0 + 2*AP + boff, b0 + 2*AP + BP + boff, rb0);
    }
    __syncthreads();

    for (int c = 0; c < nc; c++) {
        if (c + 1 < nc) {
            const int kc = (c + 1) * 16;
            ra0 = *(const float4*)(Apt + kc);
            ra1 = *(const float4*)(Apt + kc + 4);
            rb0 = *(const float4*)(Bpt + kc);
            if (NT == 128) rb1 = *(const float4*)(Bpt + kc + 4);
        }
        // ---- compute on buffer c&1 ----
        const uint32_t bse = smb + (c & 1) * STG;
        uint32_t afh[MF][4], afl[MF][4];
#pragma unroll
        for (int mf = 0; mf < MF; mf++) {
            uint32_t ad = bse + (wm * WM + mf * 16 + (lane & 15)) * 48 + ((lane >> 4) << 4);
            ldm4(afh[mf], ad);
            ldm4(afl[mf], ad + AP);
        }
        uint32_t bfh[2][4], bfl[2][4];
#pragma unroll
        for (int p = 0; p < 2; p++) {
            uint32_t bd = bse + 2*AP
                        + (wn * 32 + p * 16 + (lane & 7) + ((lane & 16) >> 1)) * 48
                        + ((lane & 8) << 1);
            ldm4(bfh[p], bd);
            ldm4(bfl[p], bd + BP);
        }
#pragma unroll
        for (int mf = 0; mf < MF; mf++)
#pragma unroll
            for (int nf = 0; nf < 4; nf++) {
                const int p = nf >> 1, s = (nf & 1) * 2;
                mma16816(acc[mf][nf], afh[mf], bfh[p][s], bfh[p][s+1]);
                mma16816(acc[mf][nf], afh[mf], bfl[p][s], bfl[p][s+1]);
                mma16816(acc[mf][nf], afl[mf], bfh[p][s], bfh[p][s+1]);
            }
        // ---- stage chunk c+1 into other buffer ----
        if (c + 1 < nc) {
            uint32_t bn = smb + ((c + 1) & 1) * STG;
            split8(bn + aoff, bn + AP + aoff, ra0, ra1);
            if (NT == 128) split8(bn + 2*AP + boff, bn + 2*AP + BP + boff, rb0, rb1);
            else           split4(bn + 2*AP + boff, bn + 2*AP + BP + boff, rb0);
            __syncthreads();
        }
    }

    // ---- epilogue ----
    const int ccol0 = blockIdx.x * NT + c_zcol * bz;
#pragma unroll
    for (int mf = 0; mf < MF; mf++) {
#pragma unroll
        for (int nf = 0; nf < 4; nf++) {
            const int col = ccol0 + wn * 32 + nf * 8 + 2 * (lane & 3);
            float bb0 = 0.f, bb1 = 0.f, sg0 = 0.f, sg1 = 0.f;
            if (EPI != 4) { bb0 = bias[col]; bb1 = bias[col + 1]; }
            if (EPI == 3) {
                sg0 = 1.f / (1.f + expf(-lam[col]));
                sg1 = 1.f / (1.f + expf(-lam[col + 1]));
            }
#pragma unroll
            for (int half = 0; half < 2; half++) {
                const int row = m0 + wm * WM + mf * 16 + (lane >> 2) + half * 8;
                const size_t off = (size_t)row * ldc + col;
                float v0 = acc[mf][nf][2*half]     + bb0;
                float v1 = acc[mf][nf][2*half + 1] + bb1;
                if (EPI == 1 || EPI == 3) {
                    float2 rv = *(const float2*)(res + off);
                    v0 += rv.x; v1 += rv.y;
                }
                if (EPI == 2) {
                    float t0 = tanhf(0.7978845608028654f * (v0 + 0.044715f * v0 * v0 * v0));
                    float t1 = tanhf(0.7978845608028654f * (v1 + 0.044715f * v1 * v1 * v1));
                    v0 = 0.5f * v0 * (1.f + t0);
                    v1 = 0.5f * v1 * (1.f + t1);
                }
                float2 o; o.x = v0; o.y = v1;
                *(float2*)(C + off) = o;
                if (EPI == 3) {
                    float2 si = *(const float2*)(ss_in + off);
                    float2 so;
                    so.x = si.x * sg0 + v0 * (1.f - sg0);
                    so.y = si.y * sg1 + v1 * (1.f - sg1);
                    *(float2*)(ss_out + off) = so;
                }
            }
        }
    }
}

// ---------------- fused: gated input + mem slot 15 + LN1 ----------------
__global__ void k_xin_ln(const float* __restrict__ x, const float* __restrict__ ssum,
                         const float* __restrict__ alpha,
                         const float* __restrict__ scale, const float* __restrict__ bias,
                         float* __restrict__ out_mem, float* __restrict__ xin,
                         float* __restrict__ y1)
{
    int gw   = (blockIdx.x * blockDim.x + threadIdx.x) >> 5;
    int lane = threadIdx.x & 31;
    if (gw >= BB) return;
    const float4* xr = (const float4*)(x    + (size_t)gw * DD);
    const float4* sr = (const float4*)(ssum + (size_t)gw * DD);
    const float4* ar = (const float4*)alpha;
    float4 v[4];
    float s = 0.f;
#pragma unroll
    for (int j = 0; j < 4; j++) {
        float4 xv = xr[lane + 32*j], sv = sr[lane + 32*j], av = ar[lane + 32*j];
        v[j].x = xv.x + sv.x * sigmoidf_(av.x);
        v[j].y = xv.y + sv.y * sigmoidf_(av.y);
        v[j].z = xv.z + sv.z * sigmoidf_(av.z);
        v[j].w = xv.w + sv.w * sigmoidf_(av.w);
        s += v[j].x + v[j].y + v[j].z + v[j].w;
    }
    float4* xo = (float4*)(xin + (size_t)gw * DD);
    float4* mo = (float4*)(out_mem + ((size_t)gw * MM + (MM-1)) * DD);
#pragma unroll
    for (int j = 0; j < 4; j++) { xo[lane + 32*j] = v[j]; mo[lane + 32*j] = v[j]; }
#pragma unroll
    for (int o = 16; o; o >>= 1) s += __shfl_xor_sync(0xffffffffu, s, o);
    float mu = s * (1.f / DD), var = 0.f;
#pragma unroll
    for (int j = 0; j < 4; j++) {
        float a = v[j].x - mu, b = v[j].y - mu, c = v[j].z - mu, d = v[j].w - mu;
        var += a*a + b*b + c*c + d*d;
    }
#pragma unroll
    for (int o = 16; o; o >>= 1) var += __shfl_xor_sync(0xffffffffu, var, o);
    float inv = rsqrtf(var * (1.f / DD) + 1e-6f);
    float4* orow = (float4*)(y1 + (size_t)gw * DD);
    const float4* sc = (const float4*)scale;
    const float4* bi = (const float4*)bias;
#pragma unroll
    for (int j = 0; j < 4; j++) {
        float4 sv = sc[lane + 32*j], bv = bi[lane + 32*j], o4;
        o4.x = (v[j].x - mu) * inv * sv.x + bv.x;
        o4.y = (v[j].y - mu) * inv * sv.y + bv.y;
        o4.z = (v[j].z - mu) * inv * sv.z + bv.z;
        o4.w = (v[j].w - mu) * inv * sv.w + bv.w;
        orow[lane + 32*j] = o4;
    }
}

// ---------------- sliding-window copy ----------------
__global__ void k_copy(const float* __restrict__ mem, float* __restrict__ out_mem)
{
    int i = blockIdx.x * blockDim.x + threadIdx.x;
    const int n = BB * (MM-1) * DD / 4;
    if (i >= n) return;
    const int per_b = (MM-1) * (DD/4);
    int b = i / per_b, r = i - b * per_b;
    int t = r >> 7, d4 = r & (DD/4 - 1);
    ((float4*)out_mem)[(size_t)(b*MM + t) * (DD/4) + d4] =
        ((const float4*)mem)[(size_t)(b*MM + t + 1) * (DD/4) + d4];
}

// ---------------- generic transpose: in[R,C] -> out[C,R] ----------------
__global__ void k_trg(const float* __restrict__ in, float* __restrict__ out, int R, int C)
{
    __shared__ float t[32][33];
    int bx = blockIdx.x * 32, by = blockIdx.y * 32;
#pragma unroll
    for (int i = 0; i < 32; i += 8)
        t[threadIdx.y + i][threadIdx.x] = in[(size_t)(by + threadIdx.y + i) * C + bx + threadIdx.x];
    __syncthreads();
#pragma unroll
    for (int i = 0; i < 32; i += 8)
        out[(size_t)(bx + threadIdx.y + i) * R + by + threadIdx.x] = t[threadIdx.x][threadIdx.y + i];
}

// ---------------- LayerNorm (LN2) ----------------
__global__ void k_ln(const float* __restrict__ in, const float* __restrict__ scale,
                     const float* __restrict__ bias, float* __restrict__ out)
{
    int gw   = (blockIdx.x * blockDim.x + threadIdx.x) >> 5;
    int lane = threadIdx.x & 31;
    if (gw >= BB) return;
    const float4* row = (const float4*)(in + (size_t)gw * DD);
    float4 v[4];
    float s = 0.f;
#pragma unroll
    for (int j = 0; j < 4; j++) {
        v[j] = row[lane + 32*j];
        s += v[j].x + v[j].y + v[j].z + v[j].w;
    }
#pragma unroll
    for (int o = 16; o; o >>= 1) s += __shfl_xor_sync(0xffffffffu, s, o);
    float mu = s * (1.f / DD), var = 0.f;
#pragma unroll
    for (int j = 0; j < 4; j++) {
        float a = v[j].x - mu, b = v[j].y - mu, c = v[j].z - mu, d = v[j].w - mu;
        var += a*a + b*b + c*c + d*d;
    }
#pragma unroll
    for (int o = 16; o; o >>= 1) var += __shfl_xor_sync(0xffffffffu, var, o);
    float inv = rsqrtf(var * (1.f / DD) + 1e-6f);
    float4* orow = (float4*)(out + (size_t)gw * DD);
    const float4* sc = (const float4*)scale;
    const float4* bi = (const float4*)bias;
#pragma unroll
    for (int j = 0; j < 4; j++) {
        float4 sv = sc[lane + 32*j], bv = bi[lane + 32*j], o4;
        o4.x = (v[j].x - mu) * inv * sv.x + bv.x;
        o4.y = (v[j].y - mu) * inv * sv.y + bv.y;
        o4.z = (v[j].z - mu) * inv * sv.z + bv.z;
        o4.w = (v[j].w - mu) * inv * sv.w + bv.w;
        orow[lane + 32*j] = o4;
    }
}

// ---------------- fused attention: block per b, warp per head ----------------
__global__ void __launch_bounds__(256) k_attn2(
    const float* __restrict__ mem2, const float* __restrict__ r,
    const float* __restrict__ q, const float* __restrict__ bk,
    float* __restrict__ wm)
{
    __shared__ float ms[MM][DD];
    const int b = blockIdx.x, tid = threadIdx.x;
    const float4* src = (const float4*)(mem2 + (size_t)b * MM * DD);
    float4* dst = (float4*)ms;
#pragma unroll
    for (int i = 0; i < 8; i++) dst[tid + 256*i] = src[tid + 256*i];
    __syncthreads();
    const int h = tid >> 5, lane = tid & 31;
    float rv[16];
    const float* rp = r + (size_t)b * (HH*DD) + h * DD;
#pragma unroll
    for (int i = 0; i < 16; i++) rv[i] = rp[i*32 + lane];
    const float* qp  = q  + (size_t)b * DD + h * HDD;
    const float* bkp = bk + h * HDD;
    float s0 = qp[lane] * bkp[lane] + qp[lane+32] * bkp[lane+32];
#pragma unroll
    for (int o = 16; o; o >>= 1) s0 += __shfl_xor_sync(0xffffffffu, s0, o);
    float sc[MM];
#pragma unroll
    for (int t = 0; t < MM; t++) {
        float p = 0.f;
#pragma unroll
        for (int i = 0; i < 16; i++) p = fmaf(rv[i], ms[t][i*32 + lane], p);
#pragma unroll
        for (int o = 16; o; o >>= 1) p += __shfl_xor_sync(0xffffffffu, p, o);
        sc[t] = (p + s0) * 0.125f;
    }
    float mx = sc[0];
#pragma unroll
    for (int t = 1; t < MM; t++) mx = fmaxf(mx, sc[t]);
    float sum = 0.f;
#pragma unroll
    for (int t = 0; t < MM; t++) { sc[t] = expf(sc[t] - mx); sum += sc[t]; }
    float inv = 1.f / sum;
    float wv[16];
#pragma unroll
    for (int i = 0; i < 16; i++) wv[i] = 0.f;
#pragma unroll
    for (int t = 0; t < MM; t++) {
        float w = sc[t] * inv;
#pragma unroll
        for (int i = 0; i < 16; i++) wv[i] = fmaf(w, ms[t][i*32 + lane], wv[i]);
    }
    float* wp = wm + (size_t)b * (HH*DD) + h * DD;
#pragma unroll
    for (int i = 0; i < 16; i++) wp[i*32 + lane] = wv[i];
}

// ---------------- launch ----------------
static const int SMEM128 = 2 * (2*128*48 + 2*128*48);   // 49152 B
static const int SMEM64  = 2 * (2*128*48 + 2*64*48);    // 36864 B

extern "C" void kernel_launch(void* const* d_in, const int* in_sizes, int n_in,
                              void* d_out, int out_size)
{
    const float* mem   = (const float*)d_in[0];
    const float* ssum  = (const float*)d_in[1];
    const float* x     = (const float*)d_in[2];
    const float* alpha = (const float*)d_in[3];
    const float* lam   = (const float*)d_in[4];
    const float* ln1s  = (const float*)d_in[5];
    const float* ln1b  = (const float*)d_in[6];
    const float* ln2s  = (const float*)d_in[7];
    const float* ln2b  = (const float*)d_in[8];
    const float* wq    = (const float*)d_in[9];
    const float* bq    = (const float*)d_in[10];
    const float* wk    = (const float*)d_in[11];
    const float* bk    = (const float*)d_in[12];
    const float* wv    = (const float*)d_in[13];
    const float* bv    = (const float*)d_in[14];
    const float* wo    = (const float*)d_in[15];
    const float* bo    = (const float*)d_in[16];
    const float* w1    = (const float*)d_in[17];
    const float* b1    = (const float*)d_in[18];
    const float* w2    = (const float*)d_in[19];
    const float* b2    = (const float*)d_in[20];

    float* out_mem  = (float*)d_out;
    float* out_ssum = out_mem + (size_t)BB * MM * DD;
    float* out_x    = out_ssum + (size_t)BB * DD;

    float *p_xin, *p_y1, *p_q, *p_r, *p_wm, *p_ctx, *p_xmid, *p_y2, *p_h;
    float *p_wqT, *p_wvT, *p_woT, *p_w1T, *p_w2T;
    cudaGetSymbolAddress((void**)&p_xin,  g_xin);
    cudaGetSymbolAddress((void**)&p_y1,   g_y1);
    cudaGetSymbolAddress((void**)&p_q,    g_q);
    cudaGetSymbolAddress((void**)&p_r,    g_r);
    cudaGetSymbolAddress((void**)&p_wm,   g_wm);
    cudaGetSymbolAddress((void**)&p_ctx,  g_ctx);
    cudaGetSymbolAddress((void**)&p_xmid, g_xmid);
    cudaGetSymbolAddress((void**)&p_y2,   g_y2);
    cudaGetSymbolAddress((void**)&p_h,    g_h);
    cudaGetSymbolAddress((void**)&p_wqT,  g_wqT);
    cudaGetSymbolAddress((void**)&p_wvT,  g_wvT);
    cudaGetSymbolAddress((void**)&p_woT,  g_woT);
    cudaGetSymbolAddress((void**)&p_w1T,  g_w1T);
    cudaGetSymbolAddress((void**)&p_w2T,  g_w2T);

    // 1) gated input + mem slot 15 + LN1
    k_xin_ln<<<BB/8, 256>>>(x, ssum, alpha, ln1s, ln1b, out_mem, p_xin, p_y1);
    // 2) shift old memory
    k_copy<<<(BB*(MM-1)*DD/4 + 255) / 256, 256>>>(mem, out_mem);
    // 3) weight transposes (B operands must be [N][K])
    k_trg<<<dim3(16, 16), dim3(32, 8)>>>(wq, p_wqT, DD, DD);
    k_trg<<<dim3(16, 16), dim3(32, 8)>>>(wv, p_wvT, DD, DD);
    k_trg<<<dim3(16, 16), dim3(32, 8)>>>(wo, p_woT, DD, DD);
    k_trg<<<dim3(64, 16), dim3(32, 8)>>>(w1, p_w1T, DD, D4X);
    k_trg<<<dim3(16, 64), dim3(32, 8)>>>(w2, p_w2T, D4X, DD);
    // 4) q = y1 @ wq + bq
    tgemm<128,0><<<dim3(4, 64, 1), 256, SMEM128>>>(p_y1, DD, 0, p_wqT, DD, 0, 0,
        bq, nullptr, p_q, DD, 0, DD, nullptr, nullptr, nullptr);
    // 5) r[b,h,j] = sum_d q[b,h*64+d] * wk[j][h*64+d]
    tgemm<128,4><<<dim3(4, 64, HH), 256, SMEM128>>>(p_q, DD, HDD, wk, DD, 0, HDD,
        nullptr, nullptr, p_r, HH*DD, DD, HDD, nullptr, nullptr, nullptr);
    // 6) attention: softmax over r·mem', weighted memory wm
    k_attn2<<<BB, 256>>>(out_mem, p_r, p_q, bk, p_wm);
    // 7) ctx[b, h*64+n] = wm[b,h,:] @ wvT[h*64+n,:] + bv
    tgemm<64,0><<<dim3(1, 64, HH), 256, SMEM64>>>(p_wm, HH*DD, DD, p_wvT, DD, HDD, 0,
        bv, nullptr, p_ctx, DD, HDD, DD, nullptr, nullptr, nullptr);
    // 8) x_mid = x_in + ctx @ wo + bo
    tgemm<128,1><<<dim3(4, 64, 1), 256, SMEM128>>>(p_ctx, DD, 0, p_woT, DD, 0, 0,
        bo, p_xin, p_xmid, DD, 0, DD, nullptr, nullptr, nullptr);
    // 9) LN2
    k_ln<<<BB/8, 256>>>(p_xmid, ln2s, ln2b, p_y2);
    // 10) h = gelu(y2 @ w1 + b1)
    tgemm<128,2><<<dim3(16, 64, 1), 256, SMEM128>>>(p_y2, DD, 0, p_w1T, DD, 0, 0,
        b1, nullptr, p_h, D4X, 0, DD, nullptr, nullptr, nullptr);
    // 11) x_out = x_mid + h @ w2 + b2 ; new_ssum = ssum*sig(lam) + x_out*(1-sig(lam))
    tgemm<128,3><<<dim3(4, 64, 1), 256, SMEM128>>>(p_h, D4X, 0, p_w2T, D4X, 0, 0,
        b2, p_xmid, out_x, DD, 0, D4X, ssum, lam, out_ssum);
}

// round 16
// speedup vs baseline: 1.0020x; 1.0011x over previous
#include <cuda_runtime.h>
#include <cuda_bf16.h>
#include <math.h>
#include <stdint.h>

#define BB   8192
#define DD   512
#define HH   8
#define MM   16
#define HDD  64
#define D4X  (4*DD)

// ---------------- scratch (device globals; no allocation allowed) ----------------
__device__ float g_xin [BB*DD];
__device__ float g_y1  [BB*DD];
__device__ float g_q   [BB*DD];
__device__ float g_r   [BB*HH*DD];
__device__ float g_wm  [BB*HH*DD];
__device__ float g_ctx [BB*DD];
__device__ float g_xmid[BB*DD];
__device__ float g_y2  [BB*DD];
__device__ float g_h   [BB*D4X];
__device__ float g_wqT [DD*DD];
__device__ float g_wvT [DD*DD];
__device__ float g_woT [DD*DD];
__device__ float g_w1T [DD*D4X];
__device__ float g_w2T [DD*D4X];

__device__ __forceinline__ float sigmoidf_(float x) { return 1.f / (1.f + expf(-x)); }

// ---------------- warp-MMA helpers (sm_80+ features; valid on base sm_103) ----------------
__device__ __forceinline__ uint32_t smem_u32(const void* p) {
    uint32_t a;
    asm("{ .reg .u64 t; cvta.to.shared.u64 t, %1; cvt.u32.u64 %0, t; }" : "=r"(a) : "l"(p));
    return a;
}
__device__ __forceinline__ void ldm4(uint32_t* r, uint32_t addr) {
    asm volatile("ldmatrix.sync.aligned.m8n8.x4.shared.b16 {%0,%1,%2,%3}, [%4];"
                 : "=r"(r[0]), "=r"(r[1]), "=r"(r[2]), "=r"(r[3]) : "r"(addr));
}
__device__ __forceinline__ void mma16816(float* d, const uint32_t* a, uint32_t b0, uint32_t b1) {
    asm volatile(
        "mma.sync.aligned.m16n8k16.row.col.f32.bf16.bf16.f32 "
        "{%0,%1,%2,%3}, {%4,%5,%6,%7}, {%8,%9}, {%0,%1,%2,%3};"
        : "+f"(d[0]), "+f"(d[1]), "+f"(d[2]), "+f"(d[3])
        : "r"(a[0]), "r"(a[1]), "r"(a[2]), "r"(a[3]), "r"(b0), "r"(b1));
}
__device__ __forceinline__ uint32_t packbf(float a, float b) {
    __nv_bfloat162 t = __floats2bfloat162_rn(a, b);
    return *reinterpret_cast<uint32_t*>(&t);
}
__device__ __forceinline__ float bfhi(float x) { return __bfloat162float(__float2bfloat16(x)); }
__device__ __forceinline__ void sts_v4(uint32_t a, uint32_t x, uint32_t y, uint32_t z, uint32_t w) {
    asm volatile("st.shared.v4.b32 [%0], {%1,%2,%3,%4};" :: "r"(a), "r"(x), "r"(y), "r"(z), "r"(w) : "memory");
}
__device__ __forceinline__ void sts_v2(uint32_t a, uint32_t x, uint32_t y) {
    asm volatile("st.shared.v2.b32 [%0], {%1,%2};" :: "r"(a), "r"(x), "r"(y) : "memory");
}

// store 8 fp32 (two float4) as bf16 hi-plane + lo-plane, 16B each
__device__ __forceinline__ void split8(uint32_t hiA, uint32_t loA, float4 v0, float4 v1) {
    float h0 = bfhi(v0.x), h1 = bfhi(v0.y), h2 = bfhi(v0.z), h3 = bfhi(v0.w);
    float h4 = bfhi(v1.x), h5 = bfhi(v1.y), h6 = bfhi(v1.z), h7 = bfhi(v1.w);
    sts_v4(hiA, packbf(h0,h1), packbf(h2,h3), packbf(h4,h5), packbf(h6,h7));
    sts_v4(loA, packbf(v0.x-h0, v0.y-h1), packbf(v0.z-h2, v0.w-h3),
                packbf(v1.x-h4, v1.y-h5), packbf(v1.z-h6, v1.w-h7));
}
__device__ __forceinline__ void split4(uint32_t hiA, uint32_t loA, float4 v) {
    float h0 = bfhi(v.x), h1 = bfhi(v.y), h2 = bfhi(v.z), h3 = bfhi(v.w);
    sts_v2(hiA, packbf(h0,h1), packbf(h2,h3));
    sts_v2(loA, packbf(v.x-h0, v.y-h1), packbf(v.z-h2, v.w-h3));
}

// ---------------- tensor-core GEMM (HMMA bf16, 3-term split, fp32 acc) ----------------
// C[128*by+m][bx*NT + c_zcol*bz + n] = sum_k A[m][a_zcol*bz+k] * Bt[bx*NT + bt_zrow*bz + n][bt_zcol*bz + k]
// EPI: 0 +bias; 1 +bias+res; 2 +bias,gelu; 3 +bias+res + gated ssum; 4 none
template<int NT, int EPI>
__global__ void __launch_bounds__(256) tgemm(
    const float* __restrict__ A, int lda, int a_zcol,
    const float* __restrict__ Bt, int ldb, int bt_zrow, int bt_zcol,
    const float* __restrict__ bias, const float* __restrict__ res,
    float* __restrict__ C, int ldc, int c_zcol, int K,
    const float* __restrict__ ss_in, const float* __restrict__ lam,
    float* __restrict__ ss_out)
{
    constexpr int WM = (NT == 128) ? 64 : 32;      // warp tile M
    constexpr int MF = WM / 16;                     // m16 fragments per warp
    constexpr int AP = 128 * 48;                    // A plane bytes (rows x 24 bf16)
    constexpr int BP = NT * 48;                     // B plane bytes
    constexpr int STG = 2 * AP + 2 * BP;            // one buffer: aHi,aLo,bHi,bLo

    extern __shared__ char smemraw[];
    const uint32_t smb = smem_u32(smemraw);

    const int tid  = threadIdx.x;
    const int lane = tid & 31;
    const int wid  = tid >> 5;
    const int wm   = (NT == 128) ? (wid & 1) : (wid & 3);
    const int wn   = (NT == 128) ? (wid >> 1) : (wid >> 2);

    const int m0 = blockIdx.y * 128;
    const int bz = blockIdx.z;
    const float* Ab = A  + a_zcol * bz + (size_t)m0 * lda;
    const float* Bb = Bt + (size_t)(blockIdx.x * NT + bt_zrow * bz) * ldb + bt_zcol * bz;

    // per-thread global->smem mapping for one k16 chunk
    const int arow = tid >> 1, akoff = (tid & 1) * 8;
    const float* Apt = Ab + (size_t)arow * lda + akoff;
    const uint32_t aoff = arow * 48 + akoff * 2;
    int brow, bkoff;
    if (NT == 128) { brow = tid >> 1; bkoff = (tid & 1) * 8; }
    else           { brow = tid >> 2; bkoff = (tid & 3) * 4; }
    const float* Bpt = Bb + (size_t)brow * ldb + bkoff;
    const uint32_t boff = brow * 48 + bkoff * 2;

    float acc[MF][4][4];
#pragma unroll
    for (int i = 0; i < MF; i++)
#pragma unroll
        for (int j = 0; j < 4; j++)
#pragma unroll
            for (int e = 0; e < 4; e++) acc[i][j][e] = 0.f;

    const int nc = K >> 4;
    float4 ra0, ra1, rb0, rb1;

    // prologue: chunk 0 -> buf 0
    ra0 = *(const float4*)(Apt);
    ra1 = *(const float4*)(Apt + 4);
    rb0 = *(const float4*)(Bpt);
    if (NT == 128) rb1 = *(const float4*)(Bpt + 4);
    {
        uint32_t b0 = smb;
        split8(b0 + aoff, b0 + AP + aoff, ra0, ra1);
        if (NT == 128) split8(b0 + 2*AP + boff, b0 + 2*AP + BP + boff, rb0, rb1);
        else           split4(b0 + 2*AP + boff, b0 + 2*AP + BP + boff, rb0);
    }
    __syncthreads();

    for (int c = 0; c < nc; c++) {
        if (c + 1 < nc) {
            const int kc = (c + 1) * 16;
            ra0 = *(const float4*)(Apt + kc);
            ra1 = *(const float4*)(Apt + kc + 4);
            rb0 = *(const float4*)(Bpt + kc);
            if (NT == 128) rb1 = *(const float4*)(Bpt + kc + 4);
        }
        // ---- compute on buffer c&1 ----
        const uint32_t bse = smb + (c & 1) * STG;
        uint32_t afh[MF][4], afl[MF][4];
#pragma unroll
        for (int mf = 0; mf < MF; mf++) {
            uint32_t ad = bse + (wm * WM + mf * 16 + (lane & 15)) * 48 + ((lane >> 4) << 4);
            ldm4(afh[mf], ad);
            ldm4(afl[mf], ad + AP);
        }
        uint32_t bfh[2][4], bfl[2][4];
#pragma unroll
        for (int p = 0; p < 2; p++) {
            uint32_t bd = bse + 2*AP
                        + (wn * 32 + p * 16 + (lane & 7) + ((lane & 16) >> 1)) * 48
                        + ((lane & 8) << 1);
            ldm4(bfh[p], bd);
            ldm4(bfl[p], bd + BP);
        }
#pragma unroll
        for (int mf = 0; mf < MF; mf++)
#pragma unroll
            for (int nf = 0; nf < 4; nf++) {
                const int p = nf >> 1, s = (nf & 1) * 2;
                mma16816(acc[mf][nf], afh[mf], bfh[p][s], bfh[p][s+1]);
                mma16816(acc[mf][nf], afh[mf], bfl[p][s], bfl[p][s+1]);
                mma16816(acc[mf][nf], afl[mf], bfh[p][s], bfh[p][s+1]);
            }
        // ---- stage chunk c+1 into other buffer ----
        if (c + 1 < nc) {
            uint32_t bn = smb + ((c + 1) & 1) * STG;
            split8(bn + aoff, bn + AP + aoff, ra0, ra1);
            if (NT == 128) split8(bn + 2*AP + boff, bn + 2*AP + BP + boff, rb0, rb1);
            else           split4(bn + 2*AP + boff, bn + 2*AP + BP + boff, rb0);
            __syncthreads();
        }
    }

    // ---- epilogue ----
    const int ccol0 = blockIdx.x * NT + c_zcol * bz;
#pragma unroll
    for (int mf = 0; mf < MF; mf++) {
#pragma unroll
        for (int nf = 0; nf < 4; nf++) {
            const int col = ccol0 + wn * 32 + nf * 8 + 2 * (lane & 3);
            float bb0 = 0.f, bb1 = 0.f, sg0 = 0.f, sg1 = 0.f;
            if (EPI != 4) { bb0 = bias[col]; bb1 = bias[col + 1]; }
            if (EPI == 3) {
                sg0 = 1.f / (1.f + expf(-lam[col]));
                sg1 = 1.f / (1.f + expf(-lam[col + 1]));
            }
#pragma unroll
            for (int half = 0; half < 2; half++) {
                const int row = m0 + wm * WM + mf * 16 + (lane >> 2) + half * 8;
                const size_t off = (size_t)row * ldc + col;
                float v0 = acc[mf][nf][2*half]     + bb0;
                float v1 = acc[mf][nf][2*half + 1] + bb1;
                if (EPI == 1 || EPI == 3) {
                    float2 rv = *(const float2*)(res + off);
                    v0 += rv.x; v1 += rv.y;
                }
                if (EPI == 2) {
                    float t0 = tanhf(0.7978845608028654f * (v0 + 0.044715f * v0 * v0 * v0));
                    float t1 = tanhf(0.7978845608028654f * (v1 + 0.044715f * v1 * v1 * v1));
                    v0 = 0.5f * v0 * (1.f + t0);
                    v1 = 0.5f * v1 * (1.f + t1);
                }
                float2 o; o.x = v0; o.y = v1;
                *(float2*)(C + off) = o;
                if (EPI == 3) {
                    float2 si = *(const float2*)(ss_in + off);
                    float2 so;
                    so.x = si.x * sg0 + v0 * (1.f - sg0);
                    so.y = si.y * sg1 + v1 * (1.f - sg1);
                    *(float2*)(ss_out + off) = so;
                }
            }
        }
    }
}

// ---------------- fused: gated input + mem slot 15 + LN1 ----------------
__global__ void k_xin_ln(const float* __restrict__ x, const float* __restrict__ ssum,
                         const float* __restrict__ alpha,
                         const float* __restrict__ scale, const float* __restrict__ bias,
                         float* __restrict__ out_mem, float* __restrict__ xin,
                         float* __restrict__ y1)
{
    int gw   = (blockIdx.x * blockDim.x + threadIdx.x) >> 5;
    int lane = threadIdx.x & 31;
    if (gw >= BB) return;
    const float4* xr = (const float4*)(x    + (size_t)gw * DD);
    const float4* sr = (const float4*)(ssum + (size_t)gw * DD);
    const float4* ar = (const float4*)alpha;
    float4 v[4];
    float s = 0.f;
#pragma unroll
    for (int j = 0; j < 4; j++) {
        float4 xv = xr[lane + 32*j], sv = sr[lane + 32*j], av = ar[lane + 32*j];
        v[j].x = xv.x + sv.x * sigmoidf_(av.x);
        v[j].y = xv.y + sv.y * sigmoidf_(av.y);
        v[j].z = xv.z + sv.z * sigmoidf_(av.z);
        v[j].w = xv.w + sv.w * sigmoidf_(av.w);
        s += v[j].x + v[j].y + v[j].z + v[j].w;
    }
    float4* xo = (float4*)(xin + (size_t)gw * DD);
    float4* mo = (float4*)(out_mem + ((size_t)gw * MM + (MM-1)) * DD);
#pragma unroll
    for (int j = 0; j < 4; j++) { xo[lane + 32*j] = v[j]; mo[lane + 32*j] = v[j]; }
#pragma unroll
    for (int o = 16; o; o >>= 1) s += __shfl_xor_sync(0xffffffffu, s, o);
    float mu = s * (1.f / DD), var = 0.f;
#pragma unroll
    for (int j = 0; j < 4; j++) {
        float a = v[j].x - mu, b = v[j].y - mu, c = v[j].z - mu, d = v[j].w - mu;
        var += a*a + b*b + c*c + d*d;
    }
#pragma unroll
    for (int o = 16; o; o >>= 1) var += __shfl_xor_sync(0xffffffffu, var, o);
    float inv = rsqrtf(var * (1.f / DD) + 1e-6f);
    float4* orow = (float4*)(y1 + (size_t)gw * DD);
    const float4* sc = (const float4*)scale;
    const float4* bi = (const float4*)bias;
#pragma unroll
    for (int j = 0; j < 4; j++) {
        float4 sv = sc[lane + 32*j], bv = bi[lane + 32*j], o4;
        o4.x = (v[j].x - mu) * inv * sv.x + bv.x;
        o4.y = (v[j].y - mu) * inv * sv.y + bv.y;
        o4.z = (v[j].z - mu) * inv * sv.z + bv.z;
        o4.w = (v[j].w - mu) * inv * sv.w + bv.w;
        orow[lane + 32*j] = o4;
    }
}

// ---------------- sliding-window copy ----------------
__global__ void k_copy(const float* __restrict__ mem, float* __restrict__ out_mem)
{
    int i = blockIdx.x * blockDim.x + threadIdx.x;
    const int n = BB * (MM-1) * DD / 4;
    if (i >= n) return;
    const int per_b = (MM-1) * (DD/4);
    int b = i / per_b, r = i - b * per_b;
    int t = r >> 7, d4 = r & (DD/4 - 1);
    ((float4*)out_mem)[(size_t)(b*MM + t) * (DD/4) + d4] =
        ((const float4*)mem)[(size_t)(b*MM + t + 1) * (DD/4) + d4];
}

// ---------------- generic transpose: in[R,C] -> out[C,R] ----------------
__global__ void k_trg(const float* __restrict__ in, float* __restrict__ out, int R, int C)
{
    __shared__ float t[32][33];
    int bx = blockIdx.x * 32, by = blockIdx.y * 32;
#pragma unroll
    for (int i = 0; i < 32; i += 8)
        t[threadIdx.y + i][threadIdx.x] = in[(size_t)(by + threadIdx.y + i) * C + bx + threadIdx.x];
    __syncthreads();
#pragma unroll
    for (int i = 0; i < 32; i += 8)
        out[(size_t)(bx + threadIdx.y + i) * R + by + threadIdx.x] = t[threadIdx.x][threadIdx.y + i];
}

// ---------------- LayerNorm (LN2) ----------------
__global__ void k_ln(const float* __restrict__ in, const float* __restrict__ scale,
                     const float* __restrict__ bias, float* __restrict__ out)
{
    int gw   = (blockIdx.x * blockDim.x + threadIdx.x) >> 5;
    int lane = threadIdx.x & 31;
    if (gw >= BB) return;
    const float4* row = (const float4*)(in + (size_t)gw * DD);
    float4 v[4];
    float s = 0.f;
#pragma unroll
    for (int j = 0; j < 4; j++) {
        v[j] = row[lane + 32*j];
        s += v[j].x + v[j].y + v[j].z + v[j].w;
    }
#pragma unroll
    for (int o = 16; o; o >>= 1) s += __shfl_xor_sync(0xffffffffu, s, o);
    float mu = s * (1.f / DD), var = 0.f;
#pragma unroll
    for (int j = 0; j < 4; j++) {
        float a = v[j].x - mu, b = v[j].y - mu, c = v[j].z - mu, d = v[j].w - mu;
        var += a*a + b*b + c*c + d*d;
    }
#pragma unroll
    for (int o = 16; o; o >>= 1) var += __shfl_xor_sync(0xffffffffu, var, o);
    float inv = rsqrtf(var * (1.f / DD) + 1e-6f);
    float4* orow = (float4*)(out + (size_t)gw * DD);
    const float4* sc = (const float4*)scale;
    const float4* bi = (const float4*)bias;
#pragma unroll
    for (int j = 0; j < 4; j++) {
        float4 sv = sc[lane + 32*j], bv = bi[lane + 32*j], o4;
        o4.x = (v[j].x - mu) * inv * sv.x + bv.x;
        o4.y = (v[j].y - mu) * inv * sv.y + bv.y;
        o4.z = (v[j].z - mu) * inv * sv.z + bv.z;
        o4.w = (v[j].w - mu) * inv * sv.w + bv.w;
        orow[lane + 32*j] = o4;
    }
}

// ---------------- fused attention: block per b, warp per head ----------------
__global__ void __launch_bounds__(256) k_attn2(
    const float* __restrict__ mem2, const float* __restrict__ r,
    const float* __restrict__ q, const float* __restrict__ bk,
    float* __restrict__ wm)
{
    __shared__ float ms[MM][DD];
    const int b = blockIdx.x, tid = threadIdx.x;
    const float4* src = (const float4*)(mem2 + (size_t)b * MM * DD);
    float4* dst = (float4*)ms;
#pragma unroll
    for (int i = 0; i < 8; i++) dst[tid + 256*i] = src[tid + 256*i];
    __syncthreads();
    const int h = tid >> 5, lane = tid & 31;
    float rv[16];
    const float* rp = r + (size_t)b * (HH*DD) + h * DD;
#pragma unroll
    for (int i = 0; i < 16; i++) rv[i] = rp[i*32 + lane];
    const float* qp  = q  + (size_t)b * DD + h * HDD;
    const float* bkp = bk + h * HDD;
    float s0 = qp[lane] * bkp[lane] + qp[lane+32] * bkp[lane+32];
#pragma unroll
    for (int o = 16; o; o >>= 1) s0 += __shfl_xor_sync(0xffffffffu, s0, o);
    float sc[MM];
#pragma unroll
    for (int t = 0; t < MM; t++) {
        float p = 0.f;
#pragma unroll
        for (int i = 0; i < 16; i++) p = fmaf(rv[i], ms[t][i*32 + lane], p);
#pragma unroll
        for (int o = 16; o; o >>= 1) p += __shfl_xor_sync(0xffffffffu, p, o);
        sc[t] = (p + s0) * 0.125f;
    }
    float mx = sc[0];
#pragma unroll
    for (int t = 1; t < MM; t++) mx = fmaxf(mx, sc[t]);
    float sum = 0.f;
#pragma unroll
    for (int t = 0; t < MM; t++) { sc[t] = expf(sc[t] - mx); sum += sc[t]; }
    float inv = 1.f / sum;
    float wv[16];
#pragma unroll
    for (int i = 0; i < 16; i++) wv[i] = 0.f;
#pragma unroll
    for (int t = 0; t < MM; t++) {
        float w = sc[t] * inv;
#pragma unroll
        for (int i = 0; i < 16; i++) wv[i] = fmaf(w, ms[t][i*32 + lane], wv[i]);
    }
    float* wp = wm + (size_t)b * (HH*DD) + h * DD;
#pragma unroll
    for (int i = 0; i < 16; i++) wp[i*32 + lane] = wv[i];
}

// ---------------- launch ----------------
static const int SMEM128 = 2 * (2*128*48 + 2*128*48);   // 49152 B
static const int SMEM64  = 2 * (2*128*48 + 2*64*48);    // 36864 B

extern "C" void kernel_launch(void* const* d_in, const int* in_sizes, int n_in,
                              void* d_out, int out_size)
{
    const float* mem   = (const float*)d_in[0];
    const float* ssum  = (const float*)d_in[1];
    const float* x     = (const float*)d_in[2];
    const float* alpha = (const float*)d_in[3];
    const float* lam   = (const float*)d_in[4];
    const float* ln1s  = (const float*)d_in[5];
    const float* ln1b  = (const float*)d_in[6];
    const float* ln2s  = (const float*)d_in[7];
    const float* ln2b  = (const float*)d_in[8];
    const float* wq    = (const float*)d_in[9];
    const float* bq    = (const float*)d_in[10];
    const float* wk    = (const float*)d_in[11];
    const float* bk    = (const float*)d_in[12];
    const float* wv    = (const float*)d_in[13];
    const float* bv    = (const float*)d_in[14];
    const float* wo    = (const float*)d_in[15];
    const float* bo    = (const float*)d_in[16];
    const float* w1    = (const float*)d_in[17];
    const float* b1    = (const float*)d_in[18];
    const float* w2    = (const float*)d_in[19];
    const float* b2    = (const float*)d_in[20];

    float* out_mem  = (float*)d_out;
    float* out_ssum = out_mem + (size_t)BB * MM * DD;
    float* out_x    = out_ssum + (size_t)BB * DD;

    float *p_xin, *p_y1, *p_q, *p_r, *p_wm, *p_ctx, *p_xmid, *p_y2, *p_h;
    float *p_wqT, *p_wvT, *p_woT, *p_w1T, *p_w2T;
    cudaGetSymbolAddress((void**)&p_xin,  g_xin);
    cudaGetSymbolAddress((void**)&p_y1,   g_y1);
    cudaGetSymbolAddress((void**)&p_q,    g_q);
    cudaGetSymbolAddress((void**)&p_r,    g_r);
    cudaGetSymbolAddress((void**)&p_wm,   g_wm);
    cudaGetSymbolAddress((void**)&p_ctx,  g_ctx);
    cudaGetSymbolAddress((void**)&p_xmid, g_xmid);
    cudaGetSymbolAddress((void**)&p_y2,   g_y2);
    cudaGetSymbolAddress((void**)&p_h,    g_h);
    cudaGetSymbolAddress((void**)&p_wqT,  g_wqT);
    cudaGetSymbolAddress((void**)&p_wvT,  g_wvT);
    cudaGetSymbolAddress((void**)&p_woT,  g_woT);
    cudaGetSymbolAddress((void**)&p_w1T,  g_w1T);
    cudaGetSymbolAddress((void**)&p_w2T,  g_w2T);

    // 1) gated input + mem slot 15 + LN1
    k_xin_ln<<<BB/8, 256>>>(x, ssum, alpha, ln1s, ln1b, out_mem, p_xin, p_y1);
    // 2) shift old memory
    k_copy<<<(BB*(MM-1)*DD/4 + 255) / 256, 256>>>(mem, out_mem);
    // 3) weight transposes (B operands must be [N][K])
    k_trg<<<dim3(16, 16), dim3(32, 8)>>>(wq, p_wqT, DD, DD);
    k_trg<<<dim3(16, 16), dim3(32, 8)>>>(wv, p_wvT, DD, DD);
    k_trg<<<dim3(16, 16), dim3(32, 8)>>>(wo, p_woT, DD, DD);
    k_trg<<<dim3(64, 16), dim3(32, 8)>>>(w1, p_w1T, DD, D4X);
    k_trg<<<dim3(16, 64), dim3(32, 8)>>>(w2, p_w2T, D4X, DD);
    // 4) q = y1 @ wq + bq
    tgemm<128,0><<<dim3(4, 64, 1), 256, SMEM128>>>(p_y1, DD, 0, p_wqT, DD, 0, 0,
        bq, nullptr, p_q, DD, 0, DD, nullptr, nullptr, nullptr);
    // 5) r[b,h,j] = sum_d q[b,h*64+d] * wk[j][h*64+d]
    tgemm<128,4><<<dim3(4, 64, HH), 256, SMEM128>>>(p_q, DD, HDD, wk, DD, 0, HDD,
        nullptr, nullptr, p_r, HH*DD, DD, HDD, nullptr, nullptr, nullptr);
    // 6) attention: softmax over r·mem', weighted memory wm
    k_attn2<<<BB, 256>>>(out_mem, p_r, p_q, bk, p_wm);
    // 7) ctx[b, h*64+n] = wm[b,h,:] @ wvT[h*64+n,:] + bv
    tgemm<64,0><<<dim3(1, 64, HH), 256, SMEM64>>>(p_wm, HH*DD, DD, p_wvT, DD, HDD, 0,
        bv, nullptr, p_ctx, DD, HDD, DD, nullptr, nullptr, nullptr);
    // 8) x_mid = x_in + ctx @ wo + bo
    tgemm<128,1><<<dim3(4, 64, 1), 256, SMEM128>>>(p_ctx, DD, 0, p_woT, DD, 0, 0,
        bo, p_xin, p_xmid, DD, 0, DD, nullptr, nullptr, nullptr);
    // 9) LN2
    k_ln<<<BB/8, 256>>>(p_xmid, ln2s, ln2b, p_y2);
    // 10) h = gelu(y2 @ w1 + b1)
    tgemm<128,2><<<dim3(16, 64, 1), 256, SMEM128>>>(p_y2, DD, 0, p_w1T, DD, 0, 0,
        b1, nullptr, p_h, D4X, 0, DD, nullptr, nullptr, nullptr);
    // 11) x_out = x_mid + h @ w2 + b2 ; new_ssum = ssum*sig(lam) + x_out*(1-sig(lam))
    tgemm<128,3><<<dim3(4, 64, 1), 256, SMEM128>>>(p_h, D4X, 0, p_w2T, D4X, 0, 0,
        b2, p_xmid, out_x, DD, 0, D4X, ssum, lam, out_ssum);
}